// round 13
// baseline (speedup 1.0000x reference)
#include <cuda_runtime.h>
#include <cuda_fp16.h>
#include <cstdint>
#include <cstddef>

// ============================================================================
// DPLSTMCell on GB300 (plain sm_103 target — no tcgen05 in this harness).
// Round 12: CTA 128x128 with 4 warps x (64x64) warp tiles, 128 threads,
// 2 CTAs/SM (same 99KB smem, mbarrier 3-stage pipeline, tanh.approx epilogue).
// Cuts LDSM traffic per chunk 96KB -> 64KB (A re-read x2 instead of x4) to
// relieve the co-limiting L1 crossbar; 32-MMA ILP per ks offsets 8-warp occ.
//   Pass 1: convert X, Hp, W_ih, W_hh fp32 -> fp16 scratch (64 MB static).
//   Pass 2: gates = [X|Hp] @ [Wih|Whh]^T + b, fused LSTM epilogue.
// ============================================================================

#define ARRN 8388608                       // 8192*1024 elements per array
__device__ __align__(256) __half g_scr[4ull * ARRN];   // Xh, Hph, Wih_h, Whh_h

// ---------------- conversion kernel ----------------
__global__ void __launch_bounds__(256)
cvt4_kernel(const float4* __restrict__ a, const float4* __restrict__ b,
            const float4* __restrict__ c, const float4* __restrict__ d) {
    const float4* src = (blockIdx.y == 0) ? a : (blockIdx.y == 1) ? b
                       : (blockIdx.y == 2) ? c : d;
    __half* dst = g_scr + (size_t)blockIdx.y * ARRN;
    int i = blockIdx.x * blockDim.x + threadIdx.x;   // 8 floats per thread
    float4 f0 = src[2 * i], f1 = src[2 * i + 1];
    union { __half h[8]; uint4 u; } p;
    p.h[0] = __float2half_rn(f0.x); p.h[1] = __float2half_rn(f0.y);
    p.h[2] = __float2half_rn(f0.z); p.h[3] = __float2half_rn(f0.w);
    p.h[4] = __float2half_rn(f1.x); p.h[5] = __float2half_rn(f1.y);
    p.h[6] = __float2half_rn(f1.z); p.h[7] = __float2half_rn(f1.w);
    ((uint4*)dst)[i] = p.u;
}

// ---------------- GEMM + LSTM kernel ----------------
#define NCHUNK 32            // K = 2048 / 64
#define STAGES 3
#define A_TILE_BYTES 16384   // 128 rows x 128 B (64 halves)
#define STAGE_BYTES  32768   // A + B
#define OFF_BIAS 0           // 128 floats (512 B)
#define OFF_MBAR 512         // full[0..2] at +0,8,16 ; empty[0..2] at +24,32,40
#define OFF_STAGE 1024
#define SMEM_TOTAL (OFF_STAGE + STAGES * STAGE_BYTES)   // 99328
#define GLDA 132             // fp32 epilogue staging row stride

__device__ __forceinline__ uint32_t smem_u32_(const void* p) {
    uint32_t a;
    asm("{ .reg .u64 t; cvta.to.shared.u64 t, %1; cvt.u32.u64 %0, t; }" : "=r"(a) : "l"(p));
    return a;
}
__device__ __forceinline__ void cp16(uint32_t s, const void* g) {
    asm volatile("cp.async.cg.shared.global [%0], [%1], 16;" :: "r"(s), "l"(g) : "memory");
}
__device__ __forceinline__ void wait_parity(uint32_t mbar, uint32_t parity) {
    asm volatile(
        "{\n\t"
        ".reg .pred P;\n\t"
        "WL_%=:\n\t"
        "mbarrier.try_wait.parity.acquire.cta.shared::cta.b64 P, [%0], %1, 0x989680;\n\t"
        "@P bra.uni WD_%=;\n\t"
        "bra.uni WL_%=;\n\t"
        "WD_%=:\n\t"
        "}"
        :: "r"(mbar), "r"(parity) : "memory");
}
#define LDSM_X4(r, addr)                                                      \
    asm volatile("ldmatrix.sync.aligned.m8n8.x4.shared.b16 {%0,%1,%2,%3}, [%4];" \
        : "=r"((r)[0]), "=r"((r)[1]), "=r"((r)[2]), "=r"((r)[3]) : "r"(addr))
#define MMA_F16(c, a, b)                                                      \
    asm volatile(                                                             \
        "mma.sync.aligned.m16n8k16.row.col.f32.f16.f16.f32 "                  \
        "{%0,%1,%2,%3}, {%4,%5,%6,%7}, {%8,%9}, {%0,%1,%2,%3};"               \
        : "+f"((c)[0]), "+f"((c)[1]), "+f"((c)[2]), "+f"((c)[3])              \
        : "r"((a)[0]), "r"((a)[1]), "r"((a)[2]), "r"((a)[3]),                 \
          "r"((b)[0]), "r"((b)[1]))

__device__ __forceinline__ float tanh_fast(float x) {
    float y;
    asm("tanh.approx.f32 %0, %1;" : "=f"(y) : "f"(x));
    return y;
}
__device__ __forceinline__ float sig_fast(float x) {
    return fmaf(0.5f, tanh_fast(0.5f * x), 0.5f);
}

__global__ void __launch_bounds__(128, 2)
lstm_gemm_kernel(const float* __restrict__ Cp,
                 const float* __restrict__ bih, const float* __restrict__ bhh,
                 float* __restrict__ out) {
    extern __shared__ char smem[];
    const uint32_t sb = smem_u32_(smem);
    const int tid = threadIdx.x;
    const int wid = tid >> 5;            // 0..3
    const int lane = tid & 31;
    const int g8 = lane >> 2;
    const int qc = lane & 3;
    const int warpM = (wid >> 1) * 64;   // 2 warps along M
    const int warpN = (wid & 1) * 64;    // 2 warps along N
    const int h0 = blockIdx.x * 32;
    const int m0 = blockIdx.y * 128;

    const __half* Xh   = g_scr;
    const __half* Hph  = g_scr + (size_t)ARRN;
    const __half* WihH = g_scr + (size_t)2 * ARRN;
    const __half* WhhH = g_scr + (size_t)3 * ARRN;

    // mbarrier init (before any cp.async arrives on them)
    if (tid == 0) {
        #pragma unroll
        for (int s = 0; s < 2 * STAGES; s++)
            asm volatile("mbarrier.init.shared.b64 [%0], 128;"
                         :: "r"(sb + OFF_MBAR + 8 * s) : "memory");
    }
    float* bias_s = (float*)(smem + OFF_BIAS);
    {   // 128 threads -> all 128 combined-bias entries
        int gr = ((tid >> 5) << 10) + h0 + (tid & 31);
        bias_s[tid] = bih[gr] + bhh[gr];
    }
    __syncthreads();

    // per-thread loader invariants: 16 cp16/chunk (8 A parts + 8 B parts)
    const int ld_r = tid >> 3;           // row 0..15 within each 16-row part
    const int ld_c = tid & 7;            // 16B col 0..7
    const uint32_t ld_smem = (uint32_t)(ld_r * 128 + ((ld_c ^ (ld_r & 7)) << 4));
    const size_t aoff = (((size_t)(m0 + ld_r)) << 10) + (ld_c << 3);
    const size_t boff = (((size_t)(h0 + ld_r)) << 10) + (ld_c << 3);
    const __half* pA = Xh + aoff;
    const __half* pB = WihH + boff;
    int ki = 0;   // next chunk index to issue

    auto issue = [&](int s) {
        uint32_t abase = sb + OFF_STAGE + s * STAGE_BYTES + ld_smem;
        uint32_t bbase = abase + A_TILE_BYTES;
        #pragma unroll
        for (int t = 0; t < 8; t++) {    // A: 8 parts of 16 rows
            cp16(abase + t * 2048, pA + ((size_t)t << 14));
        }
        #pragma unroll
        for (int g = 0; g < 4; g++) {    // B: 4 gates x 2 half-parts of 16 rows
            cp16(bbase + g * 4096,        pB + ((size_t)g << 20));
            cp16(bbase + g * 4096 + 2048, pB + ((size_t)g << 20) + (1 << 14));
        }
        // arrive full[s] when ALL of this thread's prior cp.async have landed
        asm volatile("cp.async.mbarrier.arrive.noinc.shared.b64 [%0];"
                     :: "r"(sb + OFF_MBAR + 8 * s) : "memory");
        ki++;
        if (ki == 16) { pA = Hph + aoff; pB = WhhH + boff; }
        else          { pA += 64;        pB += 64; }
    };

    float acc[4][8][4];
    #pragma unroll
    for (int mf = 0; mf < 4; mf++)
        #pragma unroll
        for (int nf = 0; nf < 8; nf++)
            #pragma unroll
            for (int e = 0; e < 4; e++) acc[mf][nf][e] = 0.f;

    // ldmatrix per-lane invariants
    const int a_l15 = lane & 15, a_hi = lane >> 4;
    const int b_nrl = (lane & 7) + ((lane >> 4) << 3);
    const int b_hi  = (lane >> 3) & 1;

    issue(0);   // chunk 0 -> stage 0
    issue(1);   // chunk 1 -> stage 1

    uint32_t fpar = 0, epar = 0;   // per-stage parity bits

    for (int k = 0; k < NCHUNK; k++) {
        int s = k % STAGES;
        // consumer: wait for stage s loads to land (all 128 threads)
        wait_parity(sb + OFF_MBAR + 8 * s, (fpar >> s) & 1);
        fpar ^= 1u << s;

        uint32_t As = sb + OFF_STAGE + s * STAGE_BYTES;
        uint32_t Bs = As + A_TILE_BYTES;

        // ---- ks = 0: fragment loads FIRST, then producer work, then MMAs ----
        uint32_t a[4][4], b[4][4];
        #pragma unroll
        for (int mf = 0; mf < 4; mf++) {
            int row = warpM + mf * 16 + a_l15;
            LDSM_X4(a[mf], As + row * 128 + ((a_hi ^ (row & 7)) << 4));
        }
        #pragma unroll
        for (int nfp = 0; nfp < 4; nfp++) {
            int row = warpN + nfp * 16 + b_nrl;
            LDSM_X4(b[nfp], Bs + row * 128 + ((b_hi ^ (row & 7)) << 4));
        }
        if (k + 2 < NCHUNK) {
            int s2 = (k + 2) % STAGES;
            if (k + 2 >= STAGES) {   // stage s2 previously held chunk k-1: wait consumed
                wait_parity(sb + OFF_MBAR + 24 + 8 * s2, (epar >> s2) & 1);
                epar ^= 1u << s2;
            }
            issue(s2);
        }
        #pragma unroll
        for (int mf = 0; mf < 4; mf++)
            #pragma unroll
            for (int nf = 0; nf < 8; nf++)
                MMA_F16(acc[mf][nf], a[mf], b[nf >> 1] + (nf & 1) * 2);

        // ---- ks = 1..3 ----
        #pragma unroll
        for (int ks = 1; ks < 4; ks++) {
            #pragma unroll
            for (int mf = 0; mf < 4; mf++) {
                int row = warpM + mf * 16 + a_l15;
                LDSM_X4(a[mf], As + row * 128 + (((2 * ks + a_hi) ^ (row & 7)) << 4));
            }
            #pragma unroll
            for (int nfp = 0; nfp < 4; nfp++) {
                int row = warpN + nfp * 16 + b_nrl;
                LDSM_X4(b[nfp], Bs + row * 128 + (((2 * ks + b_hi) ^ (row & 7)) << 4));
            }
            #pragma unroll
            for (int mf = 0; mf < 4; mf++)
                #pragma unroll
                for (int nf = 0; nf < 8; nf++)
                    MMA_F16(acc[mf][nf], a[mf], b[nf >> 1] + (nf & 1) * 2);
        }
        // consumer done with stage s
        asm volatile("mbarrier.arrive.release.cta.shared::cta.b64 _, [%0];"
                     :: "r"(sb + OFF_MBAR + 24 + 8 * s) : "memory");
    }

    // ---- epilogue: stage 128x128 fp32 gates to smem, fused LSTM pointwise ----
    __syncthreads();
    float* gbuf = (float*)(smem + OFF_STAGE);
    #pragma unroll
    for (int mf = 0; mf < 4; mf++) {
        #pragma unroll
        for (int nf = 0; nf < 8; nf++) {
            int row = warpM + mf * 16 + g8;
            int col = warpN + nf * 8 + 2 * qc;
            *(float2*)(gbuf + row * GLDA + col)       = make_float2(acc[mf][nf][0], acc[mf][nf][1]);
            *(float2*)(gbuf + (row + 8) * GLDA + col) = make_float2(acc[mf][nf][2], acc[mf][nf][3]);
        }
    }
    __syncthreads();

    float* outH = out;
    float* outC = out + ((size_t)8192 * 1024);
    const int j = lane;
    #pragma unroll
    for (int i = 0; i < 32; i++) {
        int r = wid + 4 * i;             // 4 warps x 32 rows = 128
        const float* gr = gbuf + r * GLDA + j;
        float xi = gr[0]  + bias_s[j];
        float xf = gr[32] + bias_s[32 + j];
        float xg = gr[64] + bias_s[64 + j];
        float xo = gr[96] + bias_s[96 + j];
        size_t off = (((size_t)(m0 + r)) << 10) + h0 + j;
        float cpv = Cp[off];
        float it = sig_fast(xi), ft = sig_fast(xf);
        float gt = tanh_fast(xg), ot = sig_fast(xo);
        float ct = ft * cpv + it * gt;
        float ht = ot * tanh_fast(ct);
        outH[off] = ht;
        outC[off] = ct;
    }
}

extern "C" void kernel_launch(void* const* d_in, const int* in_sizes, int n_in,
                              void* d_out, int out_size) {
    (void)in_sizes; (void)n_in; (void)out_size;
    // Pass 1: fp32 -> fp16 (X, Hp, Wih, Whh)
    dim3 cgrid(ARRN / (256 * 8), 4);
    cvt4_kernel<<<cgrid, 256>>>(
        (const float4*)d_in[0], (const float4*)d_in[1],
        (const float4*)d_in[3], (const float4*)d_in[5]);
    // Pass 2: GEMM + LSTM
    cudaFuncSetAttribute(lstm_gemm_kernel,
                         cudaFuncAttributeMaxDynamicSharedMemorySize, SMEM_TOTAL);
    dim3 grid(32, 64);
    lstm_gemm_kernel<<<grid, 128, SMEM_TOTAL>>>(
        (const float*)d_in[2], (const float*)d_in[4], (const float*)d_in[6],
        (float*)d_out);
}

// round 14
// speedup vs baseline: 1.0897x; 1.0897x over previous
#include <cuda_runtime.h>
#include <cuda_fp16.h>
#include <cstdint>
#include <cstddef>

// ============================================================================
// DPLSTMCell on GB300 (plain sm_103 target — no tcgen05 in this harness).
// Round 13: R12 config (CTA 128x128, 4 warps x 64x64, 2 CTAs/SM, mbarrier
// 3-stage pipeline) + register DOUBLE-BUFFERED ldmatrix fragments: the 8
// LDSM for K-slice ks+1 issue before the 32 MMAs of slice ks, hiding the
// ks-boundary LDSM->MMA latency that limited both prior 8-warp/SM configs.
// Register budget: acc 128 + frags 64 ~ 210 regs (launch_bounds(128,2)).
//   Pass 1: convert X, Hp, W_ih, W_hh fp32 -> fp16 scratch (64 MB static).
//   Pass 2: gates = [X|Hp] @ [Wih|Whh]^T + b, fused LSTM epilogue.
// ============================================================================

#define ARRN 8388608                       // 8192*1024 elements per array
__device__ __align__(256) __half g_scr[4ull * ARRN];   // Xh, Hph, Wih_h, Whh_h

// ---------------- conversion kernel ----------------
__global__ void __launch_bounds__(256)
cvt4_kernel(const float4* __restrict__ a, const float4* __restrict__ b,
            const float4* __restrict__ c, const float4* __restrict__ d) {
    const float4* src = (blockIdx.y == 0) ? a : (blockIdx.y == 1) ? b
                       : (blockIdx.y == 2) ? c : d;
    __half* dst = g_scr + (size_t)blockIdx.y * ARRN;
    int i = blockIdx.x * blockDim.x + threadIdx.x;   // 8 floats per thread
    float4 f0 = src[2 * i], f1 = src[2 * i + 1];
    union { __half h[8]; uint4 u; } p;
    p.h[0] = __float2half_rn(f0.x); p.h[1] = __float2half_rn(f0.y);
    p.h[2] = __float2half_rn(f0.z); p.h[3] = __float2half_rn(f0.w);
    p.h[4] = __float2half_rn(f1.x); p.h[5] = __float2half_rn(f1.y);
    p.h[6] = __float2half_rn(f1.z); p.h[7] = __float2half_rn(f1.w);
    ((uint4*)dst)[i] = p.u;
}

// ---------------- GEMM + LSTM kernel ----------------
#define NCHUNK 32            // K = 2048 / 64
#define STAGES 3
#define A_TILE_BYTES 16384   // 128 rows x 128 B (64 halves)
#define STAGE_BYTES  32768   // A + B
#define OFF_BIAS 0           // 128 floats (512 B)
#define OFF_MBAR 512         // full[0..2] at +0,8,16 ; empty[0..2] at +24,32,40
#define OFF_STAGE 1024
#define SMEM_TOTAL (OFF_STAGE + STAGES * STAGE_BYTES)   // 99328
#define GLDA 132             // fp32 epilogue staging row stride

__device__ __forceinline__ uint32_t smem_u32_(const void* p) {
    uint32_t a;
    asm("{ .reg .u64 t; cvta.to.shared.u64 t, %1; cvt.u32.u64 %0, t; }" : "=r"(a) : "l"(p));
    return a;
}
__device__ __forceinline__ void cp16(uint32_t s, const void* g) {
    asm volatile("cp.async.cg.shared.global [%0], [%1], 16;" :: "r"(s), "l"(g) : "memory");
}
__device__ __forceinline__ void wait_parity(uint32_t mbar, uint32_t parity) {
    asm volatile(
        "{\n\t"
        ".reg .pred P;\n\t"
        "WL_%=:\n\t"
        "mbarrier.try_wait.parity.acquire.cta.shared::cta.b64 P, [%0], %1, 0x989680;\n\t"
        "@P bra.uni WD_%=;\n\t"
        "bra.uni WL_%=;\n\t"
        "WD_%=:\n\t"
        "}"
        :: "r"(mbar), "r"(parity) : "memory");
}
#define LDSM_X4(r, addr)                                                      \
    asm volatile("ldmatrix.sync.aligned.m8n8.x4.shared.b16 {%0,%1,%2,%3}, [%4];" \
        : "=r"((r)[0]), "=r"((r)[1]), "=r"((r)[2]), "=r"((r)[3]) : "r"(addr))
#define MMA_F16(c, a, b)                                                      \
    asm volatile(                                                             \
        "mma.sync.aligned.m16n8k16.row.col.f32.f16.f16.f32 "                  \
        "{%0,%1,%2,%3}, {%4,%5,%6,%7}, {%8,%9}, {%0,%1,%2,%3};"               \
        : "+f"((c)[0]), "+f"((c)[1]), "+f"((c)[2]), "+f"((c)[3])              \
        : "r"((a)[0]), "r"((a)[1]), "r"((a)[2]), "r"((a)[3]),                 \
          "r"((b)[0]), "r"((b)[1]))

__device__ __forceinline__ float tanh_fast(float x) {
    float y;
    asm("tanh.approx.f32 %0, %1;" : "=f"(y) : "f"(x));
    return y;
}
__device__ __forceinline__ float sig_fast(float x) {
    return fmaf(0.5f, tanh_fast(0.5f * x), 0.5f);
}

__global__ void __launch_bounds__(128, 2)
lstm_gemm_kernel(const float* __restrict__ Cp,
                 const float* __restrict__ bih, const float* __restrict__ bhh,
                 float* __restrict__ out) {
    extern __shared__ char smem[];
    const uint32_t sb = smem_u32_(smem);
    const int tid = threadIdx.x;
    const int wid = tid >> 5;            // 0..3
    const int lane = tid & 31;
    const int g8 = lane >> 2;
    const int qc = lane & 3;
    const int warpM = (wid >> 1) * 64;   // 2 warps along M
    const int warpN = (wid & 1) * 64;    // 2 warps along N
    const int h0 = blockIdx.x * 32;
    const int m0 = blockIdx.y * 128;

    const __half* Xh   = g_scr;
    const __half* Hph  = g_scr + (size_t)ARRN;
    const __half* WihH = g_scr + (size_t)2 * ARRN;
    const __half* WhhH = g_scr + (size_t)3 * ARRN;

    // mbarrier init (before any cp.async arrives on them)
    if (tid == 0) {
        #pragma unroll
        for (int s = 0; s < 2 * STAGES; s++)
            asm volatile("mbarrier.init.shared.b64 [%0], 128;"
                         :: "r"(sb + OFF_MBAR + 8 * s) : "memory");
    }
    float* bias_s = (float*)(smem + OFF_BIAS);
    {   // 128 threads -> all 128 combined-bias entries
        int gr = ((tid >> 5) << 10) + h0 + (tid & 31);
        bias_s[tid] = bih[gr] + bhh[gr];
    }
    __syncthreads();

    // per-thread loader invariants: 16 cp16/chunk (8 A parts + 8 B parts)
    const int ld_r = tid >> 3;           // row 0..15 within each 16-row part
    const int ld_c = tid & 7;            // 16B col 0..7
    const uint32_t ld_smem = (uint32_t)(ld_r * 128 + ((ld_c ^ (ld_r & 7)) << 4));
    const size_t aoff = (((size_t)(m0 + ld_r)) << 10) + (ld_c << 3);
    const size_t boff = (((size_t)(h0 + ld_r)) << 10) + (ld_c << 3);
    const __half* pA = Xh + aoff;
    const __half* pB = WihH + boff;
    int ki = 0;   // next chunk index to issue

    auto issue = [&](int s) {
        uint32_t abase = sb + OFF_STAGE + s * STAGE_BYTES + ld_smem;
        uint32_t bbase = abase + A_TILE_BYTES;
        #pragma unroll
        for (int t = 0; t < 8; t++) {    // A: 8 parts of 16 rows
            cp16(abase + t * 2048, pA + ((size_t)t << 14));
        }
        #pragma unroll
        for (int g = 0; g < 4; g++) {    // B: 4 gates x 2 half-parts of 16 rows
            cp16(bbase + g * 4096,        pB + ((size_t)g << 20));
            cp16(bbase + g * 4096 + 2048, pB + ((size_t)g << 20) + (1 << 14));
        }
        // arrive full[s] when ALL of this thread's prior cp.async have landed
        asm volatile("cp.async.mbarrier.arrive.noinc.shared.b64 [%0];"
                     :: "r"(sb + OFF_MBAR + 8 * s) : "memory");
        ki++;
        if (ki == 16) { pA = Hph + aoff; pB = WhhH + boff; }
        else          { pA += 64;        pB += 64; }
    };

    float acc[4][8][4];
    #pragma unroll
    for (int mf = 0; mf < 4; mf++)
        #pragma unroll
        for (int nf = 0; nf < 8; nf++)
            #pragma unroll
            for (int e = 0; e < 4; e++) acc[mf][nf][e] = 0.f;

    // ldmatrix per-lane invariants
    const int a_l15 = lane & 15, a_hi = lane >> 4;
    const int b_nrl = (lane & 7) + ((lane >> 4) << 3);
    const int b_hi  = (lane >> 3) & 1;

    issue(0);   // chunk 0 -> stage 0
    issue(1);   // chunk 1 -> stage 1

    uint32_t fpar = 0, epar = 0;   // per-stage parity bits

    // double-buffered fragments (regs: 2 x (16 + 16) = 64)
    uint32_t a[2][4][4], b[2][4][4];

    for (int k = 0; k < NCHUNK; k++) {
        int s = k % STAGES;
        // consumer: wait for stage s loads to land (all 128 threads)
        wait_parity(sb + OFF_MBAR + 8 * s, (fpar >> s) & 1);
        fpar ^= 1u << s;

        uint32_t As = sb + OFF_STAGE + s * STAGE_BYTES;
        uint32_t Bs = As + A_TILE_BYTES;

        // ---- load ks=0 fragments into buffer 0 ----
        #pragma unroll
        for (int mf = 0; mf < 4; mf++) {
            int row = warpM + mf * 16 + a_l15;
            LDSM_X4(a[0][mf], As + row * 128 + ((a_hi ^ (row & 7)) << 4));
        }
        #pragma unroll
        for (int nfp = 0; nfp < 4; nfp++) {
            int row = warpN + nfp * 16 + b_nrl;
            LDSM_X4(b[0][nfp], Bs + row * 128 + ((b_hi ^ (row & 7)) << 4));
        }
        // producer work for chunk k+2 (slides into the LDSM shadow)
        if (k + 2 < NCHUNK) {
            int s2 = (k + 2) % STAGES;
            if (k + 2 >= STAGES) {
                wait_parity(sb + OFF_MBAR + 24 + 8 * s2, (epar >> s2) & 1);
                epar ^= 1u << s2;
            }
            issue(s2);
        }

        // ---- ks pipeline: prefetch ks+1 frags, then 32 MMAs on ks ----
        #pragma unroll
        for (int ks = 0; ks < 4; ks++) {
            const int cur = ks & 1, nxt = cur ^ 1;
            if (ks < 3) {
                #pragma unroll
                for (int mf = 0; mf < 4; mf++) {
                    int row = warpM + mf * 16 + a_l15;
                    LDSM_X4(a[nxt][mf],
                            As + row * 128 + (((2 * (ks + 1) + a_hi) ^ (row & 7)) << 4));
                }
                #pragma unroll
                for (int nfp = 0; nfp < 4; nfp++) {
                    int row = warpN + nfp * 16 + b_nrl;
                    LDSM_X4(b[nxt][nfp],
                            Bs + row * 128 + (((2 * (ks + 1) + b_hi) ^ (row & 7)) << 4));
                }
            } else {
                // last smem read of stage s already issued -> free the stage
                asm volatile("mbarrier.arrive.release.cta.shared::cta.b64 _, [%0];"
                             :: "r"(sb + OFF_MBAR + 24 + 8 * s) : "memory");
            }
            #pragma unroll
            for (int mf = 0; mf < 4; mf++)
                #pragma unroll
                for (int nf = 0; nf < 8; nf++)
                    MMA_F16(acc[mf][nf], a[cur][mf], b[cur][nf >> 1] + (nf & 1) * 2);
        }
    }

    // ---- epilogue: stage 128x128 fp32 gates to smem, fused LSTM pointwise ----
    __syncthreads();
    float* gbuf = (float*)(smem + OFF_STAGE);
    #pragma unroll
    for (int mf = 0; mf < 4; mf++) {
        #pragma unroll
        for (int nf = 0; nf < 8; nf++) {
            int row = warpM + mf * 16 + g8;
            int col = warpN + nf * 8 + 2 * qc;
            *(float2*)(gbuf + row * GLDA + col)       = make_float2(acc[mf][nf][0], acc[mf][nf][1]);
            *(float2*)(gbuf + (row + 8) * GLDA + col) = make_float2(acc[mf][nf][2], acc[mf][nf][3]);
        }
    }
    __syncthreads();

    float* outH = out;
    float* outC = out + ((size_t)8192 * 1024);
    const int j = lane;
    #pragma unroll
    for (int i = 0; i < 32; i++) {
        int r = wid + 4 * i;             // 4 warps x 32 rows = 128
        const float* gr = gbuf + r * GLDA + j;
        float xi = gr[0]  + bias_s[j];
        float xf = gr[32] + bias_s[32 + j];
        float xg = gr[64] + bias_s[64 + j];
        float xo = gr[96] + bias_s[96 + j];
        size_t off = (((size_t)(m0 + r)) << 10) + h0 + j;
        float cpv = Cp[off];
        float it = sig_fast(xi), ft = sig_fast(xf);
        float gt = tanh_fast(xg), ot = sig_fast(xo);
        float ct = ft * cpv + it * gt;
        float ht = ot * tanh_fast(ct);
        outH[off] = ht;
        outC[off] = ct;
    }
}

extern "C" void kernel_launch(void* const* d_in, const int* in_sizes, int n_in,
                              void* d_out, int out_size) {
    (void)in_sizes; (void)n_in; (void)out_size;
    // Pass 1: fp32 -> fp16 (X, Hp, Wih, Whh)
    dim3 cgrid(ARRN / (256 * 8), 4);
    cvt4_kernel<<<cgrid, 256>>>(
        (const float4*)d_in[0], (const float4*)d_in[1],
        (const float4*)d_in[3], (const float4*)d_in[5]);
    // Pass 2: GEMM + LSTM
    cudaFuncSetAttribute(lstm_gemm_kernel,
                         cudaFuncAttributeMaxDynamicSharedMemorySize, SMEM_TOTAL);
    dim3 grid(32, 64);
    lstm_gemm_kernel<<<grid, 128, SMEM_TOTAL>>>(
        (const float*)d_in[2], (const float*)d_in[4], (const float*)d_in[6],
        (float*)d_out);
}